// round 5
// baseline (speedup 1.0000x reference)
#include <cuda_runtime.h>
#include <cuda_fp16.h>
#include <cstdint>
#include <math.h>

#define BATCH 4
#define SEQ 2048
#define DMODEL 1024
#define NHEADS 16
#define DHEAD 64
#define MTOT (BATCH*SEQ)   // 8192

// ---------------- scratch (device globals: allocation-free) ----------------
__device__ __half g_Ah[(size_t)3*MTOT*DMODEL];     // q,k,v converted to half
__device__ __half g_Wh[(size_t)4*DMODEL*DMODEL];   // Wq,Wk,Wv,Wo converted
__device__ __half g_Qh[(size_t)MTOT*DMODEL];       // [B,H,L,Dh]
__device__ __half g_Kh[(size_t)MTOT*DMODEL];
__device__ __half g_Vh[(size_t)MTOT*DMODEL];
__device__ __half g_Oh[(size_t)MTOT*DMODEL];       // attn out [B,L,D] half

// ---------------- asm helpers ----------------
__device__ __forceinline__ void mma16(float* c, const uint32_t* a, const uint32_t* b){
    asm volatile("mma.sync.aligned.m16n8k16.row.col.f32.f16.f16.f32 "
        "{%0,%1,%2,%3}, {%4,%5,%6,%7}, {%8,%9}, {%0,%1,%2,%3};"
        : "+f"(c[0]), "+f"(c[1]), "+f"(c[2]), "+f"(c[3])
        : "r"(a[0]), "r"(a[1]), "r"(a[2]), "r"(a[3]), "r"(b[0]), "r"(b[1]));
}
__device__ __forceinline__ void ldsm4(uint32_t* r, uint32_t addr){
    asm volatile("ldmatrix.sync.aligned.m8n8.x4.shared.b16 {%0,%1,%2,%3}, [%4];"
        : "=r"(r[0]), "=r"(r[1]), "=r"(r[2]), "=r"(r[3]) : "r"(addr));
}
__device__ __forceinline__ void ldsm4t(uint32_t* r, uint32_t addr){
    asm volatile("ldmatrix.sync.aligned.m8n8.x4.trans.shared.b16 {%0,%1,%2,%3}, [%4];"
        : "=r"(r[0]), "=r"(r[1]), "=r"(r[2]), "=r"(r[3]) : "r"(addr));
}
__device__ __forceinline__ void cpa16(uint32_t dst, const void* src){
    asm volatile("cp.async.cg.shared.global [%0], [%1], 16;" :: "r"(dst), "l"(src));
}
#define CP_COMMIT()  asm volatile("cp.async.commit_group;")
#define CP_WAIT(N)   asm volatile("cp.async.wait_group %0;" :: "n"(N))
__device__ __forceinline__ float ex2f(float x){
    float y; asm("ex2.approx.f32 %0, %1;" : "=f"(y) : "f"(x)); return y;
}
__device__ __forceinline__ uint32_t packh2(float a, float b){
    __half2 h = __floats2half2_rn(a, b);
    return *reinterpret_cast<uint32_t*>(&h);
}
__device__ __forceinline__ uint32_t smem_u32(const void* p){
    return (uint32_t)__cvta_generic_to_shared(p);
}

// ---------------- prepass: fp32 -> fp16 ----------------
__global__ void f2h_kernel(const float* __restrict__ s, __half* __restrict__ d, int n4){
    int i = blockIdx.x * blockDim.x + threadIdx.x;
    if (i < n4) {
        float4 v = reinterpret_cast<const float4*>(s)[i];
        uint2 o;
        o.x = packh2(v.x, v.y);
        o.y = packh2(v.z, v.w);
        reinterpret_cast<uint2*>(d)[i] = o;
    }
}

// ============================================================================
// GEMM: C[8192,1024] = A[8192,1024] @ W[1024,1024] + bias (half in, fp32 acc)
// Block 128x256, 8 warps (2m x 4n), warp tile 64x64, BK=32, 3-stage cp.async.
// ============================================================================
#define GA_STRIDE 80      // bytes per A smem row (32+8 halves)
#define GB_STRIDE 528     // bytes per B smem row (256+8 halves)
#define GA_STAGE 10240    // 128*80
#define GB_STAGE 16896    // 32*528
#define STG (GA_STAGE + GB_STAGE)        // 27136
#define G_STAGES 3
#define G_SMEM (G_STAGES*STG)            // 81408

__global__ __launch_bounds__(256, 1) void gemm_f16(
    const __half* __restrict__ A, const __half* __restrict__ W,
    const float* __restrict__ bias, float* __restrict__ outF, int outMode)
{
    extern __shared__ __align__(16) char sm[];
    const uint32_t smBase = smem_u32(sm);

    const int tid = threadIdx.x;
    const int warpId = tid >> 5, lane = tid & 31;
    const int g = lane >> 2, t = lane & 3;
    const int wm = warpId & 1;        // 2 warps along M (64 rows each)
    const int wn = warpId >> 1;       // 4 warps along N (64 cols each)
    const int m0 = blockIdx.y * 128;
    const int n0 = blockIdx.x * 256;

    // cp.async coords
    const int ar = tid >> 2, ac = tid & 3;       // A: rows ar, ar+64; 4x16B chunks/row
    const int br = tid >> 5, bc = tid & 31;      // B: rows br+8p (p=0..3); 32 chunks/row
    const __half* Abase = A + (size_t)(m0 + ar) * DMODEL + ac * 8;
    const __half* Wbase = W + (size_t)br * DMODEL + n0 + bc * 8;
    const uint32_t aDst = ar * GA_STRIDE + ac * 16;
    const uint32_t bDst = br * GB_STRIDE + bc * 16;

    // ldmatrix per-lane offsets
    const uint32_t aFragOff = (uint32_t)((wm*64 + (lane & 15)) * GA_STRIDE + (lane >> 4) * 16);
    const uint32_t bFragOff = (uint32_t)((lane & 15) * GB_STRIDE + wn*128 + (lane >> 4) * 16);

    float acc[4][8][4];
    #pragma unroll
    for (int mt = 0; mt < 4; mt++)
        #pragma unroll
        for (int nt = 0; nt < 8; nt++)
            #pragma unroll
            for (int e = 0; e < 4; e++) acc[mt][nt][e] = 0.f;

    const int KT = DMODEL / 32;   // 32 k-tiles

    #pragma unroll
    for (int s = 0; s < G_STAGES; s++) {
        const __half* Asrc = Abase + s * 32;
        const __half* Wsrc = Wbase + (size_t)s * 32 * DMODEL;
        uint32_t a = smBase + s * STG + aDst;
        uint32_t b = smBase + s * STG + GA_STAGE + bDst;
        cpa16(a,                Asrc);
        cpa16(a + 64*GA_STRIDE, Asrc + (size_t)64 * DMODEL);
        #pragma unroll
        for (int p = 0; p < 4; p++)
            cpa16(b + p * (8*GB_STRIDE), Wsrc + (size_t)p * 8 * DMODEL);
        CP_COMMIT();
    }

    for (int i = 0; i < KT; i++) {
        CP_WAIT(2);
        __syncthreads();
        const int st = i % G_STAGES;
        const uint32_t aS = smBase + st * STG;
        const uint32_t bS = aS + GA_STAGE;

        #pragma unroll
        for (int ks = 0; ks < 32; ks += 16) {
            uint32_t af[4][4], bf[4][4];
            #pragma unroll
            for (int mt = 0; mt < 4; mt++)
                ldsm4(af[mt], aS + aFragOff + mt * (16*GA_STRIDE) + ks * 2);
            #pragma unroll
            for (int np = 0; np < 4; np++)
                ldsm4t(bf[np], bS + bFragOff + ks * GB_STRIDE + np * 32);
            #pragma unroll
            for (int mt = 0; mt < 4; mt++)
                #pragma unroll
                for (int np = 0; np < 4; np++) {
                    mma16(acc[mt][2*np],   af[mt], bf[np]);
                    mma16(acc[mt][2*np+1], af[mt], bf[np] + 2);
                }
        }
        __syncthreads();
        if (i + G_STAGES < KT) {
            const int kt = i + G_STAGES;
            const __half* Asrc = Abase + kt * 32;
            const __half* Wsrc = Wbase + (size_t)kt * 32 * DMODEL;
            uint32_t a = smBase + st * STG + aDst;
            uint32_t b = smBase + st * STG + GA_STAGE + bDst;
            cpa16(a,                Asrc);
            cpa16(a + 64*GA_STRIDE, Asrc + (size_t)64 * DMODEL);
            #pragma unroll
            for (int p = 0; p < 4; p++)
                cpa16(b + p * (8*GB_STRIDE), Wsrc + (size_t)p * 8 * DMODEL);
        }
        CP_COMMIT();
    }

    // epilogue
    __half* splitDst = (outMode == 1) ? g_Qh : (outMode == 2) ? g_Kh : g_Vh;
    #pragma unroll
    for (int mt = 0; mt < 4; mt++) {
        #pragma unroll
        for (int nt = 0; nt < 8; nt++) {
            int c = n0 + wn*64 + nt*8 + 2*t;
            float b0 = bias[c], b1 = bias[c+1];
            #pragma unroll
            for (int hh = 0; hh < 2; hh++) {
                int r = m0 + wm*64 + mt*16 + g + hh*8;
                float v0 = acc[mt][nt][2*hh]   + b0;
                float v1 = acc[mt][nt][2*hh+1] + b1;
                if (outMode == 0) {
                    float2 fv = make_float2(v0, v1);
                    *reinterpret_cast<float2*>(&outF[(size_t)r * DMODEL + c]) = fv;
                } else {
                    int b = r >> 11, l = r & (SEQ-1);
                    int h = c >> 6, d = c & (DHEAD-1);
                    size_t idx = ((((size_t)b*NHEADS + h)*SEQ) + l)*DHEAD + d;
                    *reinterpret_cast<uint32_t*>(&splitDst[idx]) = packh2(v0, v1);
                }
            }
        }
    }
}

// ============================================================================
// Flash attention (causal, fp16 mma). Grid (16, 64), 256 threads = 8 warps.
// BM=128, BN=64. K/V double-buffered cp.async; P in registers (FA2).
// ============================================================================
#define AT_STRIDE 144             // bytes per smem row (64+8 halves)
#define AT_TILE   (64*AT_STRIDE)  // 9216
#define AQ_TILE   (128*AT_STRIDE) // 18432
#define ATT_SMEM  (AQ_TILE + 4*AT_TILE)  // 55296

__global__ __launch_bounds__(256) void attn_kernel()
{
    extern __shared__ __align__(16) char sm[];
    const uint32_t smBase = smem_u32(sm);
    const uint32_t sQ  = smBase;
    const uint32_t sK0 = smBase + AQ_TILE;
    const uint32_t sV0 = sK0 + 2*AT_TILE;

    const int tid = threadIdx.x;
    const int warp = tid >> 5, lane = tid & 31;
    const int g = lane >> 2, t = lane & 3;
    const int bh = blockIdx.y;
    const int qt = (int)(gridDim.x - 1 - blockIdx.x);   // longest-first
    const int q0 = qt * 128;
    const int JMAX = 2*qt + 1;

    const __half* Qp = g_Qh + (size_t)bh * SEQ * DHEAD;
    const __half* Kp = g_Kh + (size_t)bh * SEQ * DHEAD;
    const __half* Vp = g_Vh + (size_t)bh * SEQ * DHEAD;

    // ---- stage Q (128x64) then K0/V0 (64x64 each)
    {
        const __half* Qs = Qp + (size_t)q0 * DHEAD;
        #pragma unroll
        for (int p = 0; p < 4; p++) {
            int idx = tid + p*256;
            int r = idx >> 3, c = idx & 7;
            cpa16(sQ + r*AT_STRIDE + c*16, Qs + r*DHEAD + c*8);
        }
        CP_COMMIT();
        #pragma unroll
        for (int p = 0; p < 2; p++) {
            int idx = tid + p*256;
            int r = idx >> 3, c = idx & 7;
            cpa16(sK0 + r*AT_STRIDE + c*16, Kp + r*DHEAD + c*8);
            cpa16(sV0 + r*AT_STRIDE + c*16, Vp + r*DHEAD + c*8);
        }
        CP_COMMIT();
    }
    CP_WAIT(1);          // Q ready
    __syncthreads();

    uint32_t qf[4][4];
    {
        uint32_t qOff = sQ + (uint32_t)((warp*16 + (lane & 15)) * AT_STRIDE + (lane >> 4) * 16);
        #pragma unroll
        for (int ks = 0; ks < 4; ks++)
            ldsm4(qf[ks], qOff + ks * 32);
    }

    const uint32_t kOff = (uint32_t)(((lane & 7) + ((lane >> 4) << 3)) * AT_STRIDE + ((lane >> 3) & 1) * 16);
    const uint32_t vOff = (uint32_t)((lane & 15) * AT_STRIDE + (lane >> 4) * 16);

    float oacc[8][4];
    #pragma unroll
    for (int nt = 0; nt < 8; nt++)
        #pragma unroll
        for (int e = 0; e < 4; e++) oacc[nt][e] = 0.f;
    float mrun[2] = {-INFINITY, -INFINITY};
    float lrun[2] = {0.f, 0.f};
    const float cl2e = 0.125f * 1.4426950408889634f;

    for (int j = 0; j <= JMAX; j++) {
        if (j < JMAX) {
            const __half* Ks = Kp + (size_t)(j+1) * 64 * DHEAD;
            const __half* Vs = Vp + (size_t)(j+1) * 64 * DHEAD;
            uint32_t kb = sK0 + ((j+1) & 1) * AT_TILE;
            uint32_t vb = sV0 + ((j+1) & 1) * AT_TILE;
            #pragma unroll
            for (int p = 0; p < 2; p++) {
                int idx = tid + p*256;
                int r = idx >> 3, c = idx & 7;
                cpa16(kb + r*AT_STRIDE + c*16, Ks + r*DHEAD + c*8);
                cpa16(vb + r*AT_STRIDE + c*16, Vs + r*DHEAD + c*8);
            }
        }
        CP_COMMIT();
        CP_WAIT(1);
        __syncthreads();

        const uint32_t kB = sK0 + (j & 1) * AT_TILE;
        const uint32_t vB = sV0 + (j & 1) * AT_TILE;

        // ---- S = Q K^T
        float s[8][4];
        #pragma unroll
        for (int nt = 0; nt < 8; nt++)
            #pragma unroll
            for (int e = 0; e < 4; e++) s[nt][e] = 0.f;

        #pragma unroll
        for (int ks = 0; ks < 4; ks++) {
            #pragma unroll
            for (int np = 0; np < 4; np++) {
                uint32_t bf[4];
                ldsm4(bf, kB + kOff + np * (16*AT_STRIDE) + ks * 32);
                mma16(s[2*np],   qf[ks], bf);
                mma16(s[2*np+1], qf[ks], bf + 2);
            }
        }

        // ---- causal mask (only last two j-tiles touch the diagonal band)
        if (j >= 2*qt) {
            #pragma unroll
            for (int nt = 0; nt < 8; nt++) {
                #pragma unroll
                for (int e = 0; e < 4; e++) {
                    int rq = q0 + warp*16 + g + ((e >= 2) ? 8 : 0);
                    int ck = j*64 + nt*8 + 2*t + (e & 1);
                    if (ck > rq) s[nt][e] = -INFINITY;
                }
            }
        }

        // ---- online softmax (rows g, g+8 within warp's 16-row strip)
        #pragma unroll
        for (int hh = 0; hh < 2; hh++) {
            float mx = -INFINITY;
            #pragma unroll
            for (int nt = 0; nt < 8; nt++)
                mx = fmaxf(mx, fmaxf(s[nt][2*hh], s[nt][2*hh+1]));
            mx = fmaxf(mx, __shfl_xor_sync(0xffffffffu, mx, 1));
            mx = fmaxf(mx, __shfl_xor_sync(0xffffffffu, mx, 2));
            float mnew = fmaxf(mrun[hh], mx);
            float corr = ex2f((mrun[hh] - mnew) * cl2e);
            float mc = mnew * cl2e;
            mrun[hh] = mnew;
            float sum = 0.f;
            #pragma unroll
            for (int nt = 0; nt < 8; nt++) {
                float p0 = ex2f(fmaf(s[nt][2*hh],   cl2e, -mc)); s[nt][2*hh]   = p0;
                float p1 = ex2f(fmaf(s[nt][2*hh+1], cl2e, -mc)); s[nt][2*hh+1] = p1;
                sum += p0 + p1;
            }
            sum += __shfl_xor_sync(0xffffffffu, sum, 1);
            sum += __shfl_xor_sync(0xffffffffu, sum, 2);
            lrun[hh] = lrun[hh] * corr + sum;
            #pragma unroll
            for (int nt = 0; nt < 8; nt++) {
                oacc[nt][2*hh]   *= corr;
                oacc[nt][2*hh+1] *= corr;
            }
        }

        // ---- O += P @ V (P from registers)
        #pragma unroll
        for (int kb = 0; kb < 4; kb++) {
            uint32_t pa[4];
            pa[0] = packh2(s[2*kb][0],   s[2*kb][1]);
            pa[1] = packh2(s[2*kb][2],   s[2*kb][3]);
            pa[2] = packh2(s[2*kb+1][0], s[2*kb+1][1]);
            pa[3] = packh2(s[2*kb+1][2], s[2*kb+1][3]);
            #pragma unroll
            for (int np = 0; np < 4; np++) {
                uint32_t bf[4];
                ldsm4t(bf, vB + vOff + kb * (16*AT_STRIDE) + np * 32);
                mma16(oacc[2*np],   pa, bf);
                mma16(oacc[2*np+1], pa, bf + 2);
            }
        }
        __syncthreads();
    }

    // ---- epilogue: normalize, half2 store into g_Oh [B, L, D]
    const int b = bh / NHEADS, h = bh % NHEADS;
    float linv[2] = {1.f / lrun[0], 1.f / lrun[1]};
    #pragma unroll
    for (int nt = 0; nt < 8; nt++) {
        #pragma unroll
        for (int hh = 0; hh < 2; hh++) {
            int r = q0 + warp*16 + g + hh*8;
            int d = nt*8 + 2*t;
            size_t idx = ((size_t)b*SEQ + r) * DMODEL + h*DHEAD + d;
            *reinterpret_cast<uint32_t*>(&g_Oh[idx]) =
                packh2(oacc[nt][2*hh] * linv[hh], oacc[nt][2*hh+1] * linv[hh]);
        }
    }
}

// ============================================================================
extern "C" void kernel_launch(void* const* d_in, const int* in_sizes, int n_in,
                              void* d_out, int out_size)
{
    const float* q  = (const float*)d_in[0];
    const float* k  = (const float*)d_in[1];
    const float* v  = (const float*)d_in[2];
    const float* Wq = (const float*)d_in[3];
    const float* bq = (const float*)d_in[4];
    const float* Wk = (const float*)d_in[5];
    const float* bk = (const float*)d_in[6];
    const float* Wv = (const float*)d_in[7];
    const float* bv = (const float*)d_in[8];
    const float* Wo = (const float*)d_in[9];
    const float* bo = (const float*)d_in[10];
    float* out = (float*)d_out;

    __half *Ah, *Wh, *Oh;
    cudaGetSymbolAddress((void**)&Ah, g_Ah);
    cudaGetSymbolAddress((void**)&Wh, g_Wh);
    cudaGetSymbolAddress((void**)&Oh, g_Oh);

    cudaFuncSetAttribute(gemm_f16, cudaFuncAttributeMaxDynamicSharedMemorySize, G_SMEM);
    cudaFuncSetAttribute(attn_kernel, cudaFuncAttributeMaxDynamicSharedMemorySize, ATT_SMEM);

    const size_t NIN = (size_t)MTOT * DMODEL;
    const size_t NW  = (size_t)DMODEL * DMODEL;

    // prepass: fp32 -> fp16
    f2h_kernel<<<(int)(NIN/4/256), 256>>>(q,  Ah,          (int)(NIN/4));
    f2h_kernel<<<(int)(NIN/4/256), 256>>>(k,  Ah + NIN,    (int)(NIN/4));
    f2h_kernel<<<(int)(NIN/4/256), 256>>>(v,  Ah + 2*NIN,  (int)(NIN/4));
    f2h_kernel<<<(int)(NW/4/256),  256>>>(Wq, Wh,          (int)(NW/4));
    f2h_kernel<<<(int)(NW/4/256),  256>>>(Wk, Wh + NW,     (int)(NW/4));
    f2h_kernel<<<(int)(NW/4/256),  256>>>(Wv, Wh + 2*NW,   (int)(NW/4));
    f2h_kernel<<<(int)(NW/4/256),  256>>>(Wo, Wh + 3*NW,   (int)(NW/4));

    dim3 gg(DMODEL/256, MTOT/128);   // (4, 64)
    gemm_f16<<<gg, 256, G_SMEM>>>(Ah,         Wh,        bq, nullptr, 1);
    gemm_f16<<<gg, 256, G_SMEM>>>(Ah + NIN,   Wh + NW,   bk, nullptr, 2);
    gemm_f16<<<gg, 256, G_SMEM>>>(Ah + 2*NIN, Wh + 2*NW, bv, nullptr, 3);

    dim3 ga(SEQ/128, BATCH*NHEADS);  // (16, 64)
    attn_kernel<<<ga, 256, ATT_SMEM>>>();

    gemm_f16<<<gg, 256, G_SMEM>>>(Oh, Wh + 3*NW, bo, out, 0);
}

// round 6
// speedup vs baseline: 1.1088x; 1.1088x over previous
#include <cuda_runtime.h>
#include <cuda_fp16.h>
#include <cstdint>
#include <math.h>

#define BATCH 4
#define SEQ 2048
#define DMODEL 1024
#define NHEADS 16
#define DHEAD 64
#define MTOT (BATCH*SEQ)   // 8192
#define NIN ((size_t)MTOT*DMODEL)    // 8388608
#define NW  ((size_t)DMODEL*DMODEL)  // 1048576

// ---------------- scratch (device globals: allocation-free) ----------------
__device__ __half g_Ah[(size_t)3*NIN];   // q,k,v converted to half
__device__ __half g_Wh[(size_t)4*NW];    // Wq,Wk,Wv,Wo converted
__device__ __half g_Qh[NIN];             // [B,H,L,Dh]
__device__ __half g_Kh[NIN];
__device__ __half g_Vh[NIN];
__device__ __half g_Oh[NIN];             // attn out [B,L,D] half

// ---------------- asm helpers ----------------
__device__ __forceinline__ void mma16(float* c, const uint32_t* a, const uint32_t* b){
    asm volatile("mma.sync.aligned.m16n8k16.row.col.f32.f16.f16.f32 "
        "{%0,%1,%2,%3}, {%4,%5,%6,%7}, {%8,%9}, {%0,%1,%2,%3};"
        : "+f"(c[0]), "+f"(c[1]), "+f"(c[2]), "+f"(c[3])
        : "r"(a[0]), "r"(a[1]), "r"(a[2]), "r"(a[3]), "r"(b[0]), "r"(b[1]));
}
__device__ __forceinline__ void ldsm4(uint32_t* r, uint32_t addr){
    asm volatile("ldmatrix.sync.aligned.m8n8.x4.shared.b16 {%0,%1,%2,%3}, [%4];"
        : "=r"(r[0]), "=r"(r[1]), "=r"(r[2]), "=r"(r[3]) : "r"(addr));
}
__device__ __forceinline__ void ldsm4t(uint32_t* r, uint32_t addr){
    asm volatile("ldmatrix.sync.aligned.m8n8.x4.trans.shared.b16 {%0,%1,%2,%3}, [%4];"
        : "=r"(r[0]), "=r"(r[1]), "=r"(r[2]), "=r"(r[3]) : "r"(addr));
}
__device__ __forceinline__ void cpa16(uint32_t dst, const void* src){
    asm volatile("cp.async.cg.shared.global [%0], [%1], 16;" :: "r"(dst), "l"(src));
}
#define CP_COMMIT()  asm volatile("cp.async.commit_group;")
#define CP_WAIT(N)   asm volatile("cp.async.wait_group %0;" :: "n"(N))
__device__ __forceinline__ float ex2f(float x){
    float y; asm("ex2.approx.f32 %0, %1;" : "=f"(y) : "f"(x)); return y;
}
__device__ __forceinline__ uint32_t packh2(float a, float b){
    __half2 h = __floats2half2_rn(a, b);
    return *reinterpret_cast<uint32_t*>(&h);
}
__device__ __forceinline__ uint32_t smem_u32(const void* p){
    return (uint32_t)__cvta_generic_to_shared(p);
}

// ---------------- prepass: fp32 -> fp16, all 7 tensors in ONE launch --------
// grid (8192, 7): y in [0,3) -> inputs (2M float4 each), y in [3,7) -> weights
__global__ void f2h_all(const float* __restrict__ q, const float* __restrict__ k,
                        const float* __restrict__ v, const float* __restrict__ Wq,
                        const float* __restrict__ Wk, const float* __restrict__ Wv,
                        const float* __restrict__ Wo)
{
    const int y = blockIdx.y;
    const float* src;
    __half* dst;
    int n4;
    if (y < 3) {
        src = (y == 0) ? q : (y == 1) ? k : v;
        dst = g_Ah + (size_t)y * NIN;
        n4 = (int)(NIN / 4);
    } else {
        if (blockIdx.x >= 1024) return;
        src = (y == 3) ? Wq : (y == 4) ? Wk : (y == 5) ? Wv : Wo;
        dst = g_Wh + (size_t)(y - 3) * NW;
        n4 = (int)(NW / 4);
    }
    int i = blockIdx.x * blockDim.x + threadIdx.x;
    if (i < n4) {
        float4 val = reinterpret_cast<const float4*>(src)[i];
        uint2 o;
        o.x = packh2(val.x, val.y);
        o.y = packh2(val.z, val.w);
        reinterpret_cast<uint2*>(dst)[i] = o;
    }
}

// ============================================================================
// GEMM (R2-validated config): C[8192,1024] = A @ W + bias, half in, fp32 acc.
// Block 128x128, 8 warps (4m x 2n), warp 32x64, BK=32, 3-stage cp.async.
// qkvMode=1: blockIdx.z in {0,1,2} selects (A,W,bias,outMode z+1) for Q/K/V.
// qkvMode=0: A=g_Oh, W=g_Wh+3*NW, fp32 flat output.
// ============================================================================
#define GA_STRIDE 80     // bytes per A smem row (32+8 halves)
#define GB_STRIDE 272    // bytes per B smem row (128+8 halves)
#define GA_STAGE 10240   // 128*80
#define GB_STAGE 8704    // 32*272
#define G_STAGES 3
#define G_SMEM (G_STAGES*(GA_STAGE+GB_STAGE))   // 56832

__global__ __launch_bounds__(256) void gemm_f16(
    const float* __restrict__ b0, const float* __restrict__ b1,
    const float* __restrict__ b2, float* __restrict__ outF, int qkvMode)
{
    const int z = qkvMode ? (int)blockIdx.z : 3;
    const __half* A = qkvMode ? (g_Ah + (size_t)z * NIN) : g_Oh;
    const __half* W = g_Wh + (size_t)z * NW;
    const float* bias = (z == 0 || z == 3) ? b0 : (z == 1) ? b1 : b2;
    const int outMode = qkvMode ? (z + 1) : 0;

    extern __shared__ __align__(16) char sm[];
    const uint32_t smBase = smem_u32(sm);
    const uint32_t sA0 = smBase;
    const uint32_t sB0 = smBase + G_STAGES * GA_STAGE;

    const int tid = threadIdx.x;
    const int warpId = tid >> 5, lane = tid & 31;
    const int g = lane >> 2, t = lane & 3;
    const int wm = warpId & 3, wn = warpId >> 2;
    const int m0 = blockIdx.y * 128;
    const int n0 = blockIdx.x * 128;

    // cp.async coords
    const int am = tid >> 2, akc = tid & 3;          // A: rows am, am+64
    const int bk = tid >> 4, bnc = tid & 15;         // B: rows bk, bk+16
    const __half* Abase = A + (size_t)(m0 + am) * DMODEL + akc * 8;
    const __half* Wbase = W + (size_t)bk * DMODEL + n0 + bnc * 8;
    const uint32_t aDst = am * GA_STRIDE + akc * 16;
    const uint32_t bDst = bk * GB_STRIDE + bnc * 16;

    // ldmatrix per-lane offsets
    const uint32_t aFragOff = (uint32_t)((wm*32 + (lane & 15)) * GA_STRIDE + (lane >> 4) * 16);
    const uint32_t bFragOff = (uint32_t)((lane & 15) * GB_STRIDE + wn*128 + (lane >> 4) * 16);

    float acc[2][8][4];
    #pragma unroll
    for (int mt = 0; mt < 2; mt++)
        #pragma unroll
        for (int nt = 0; nt < 8; nt++)
            #pragma unroll
            for (int e = 0; e < 4; e++) acc[mt][nt][e] = 0.f;

    const int KT = DMODEL / 32;  // 32 k-tiles

    #pragma unroll
    for (int s = 0; s < G_STAGES; s++) {
        const __half* Asrc = Abase + s * 32;
        const __half* Wsrc = Wbase + (size_t)s * 32 * DMODEL;
        uint32_t a = sA0 + s * GA_STAGE + aDst;
        uint32_t b = sB0 + s * GB_STAGE + bDst;
        cpa16(a,                 Asrc);
        cpa16(a + 64*GA_STRIDE,  Asrc + (size_t)64 * DMODEL);
        cpa16(b,                 Wsrc);
        cpa16(b + 16*GB_STRIDE,  Wsrc + (size_t)16 * DMODEL);
        CP_COMMIT();
    }

    for (int i = 0; i < KT; i++) {
        CP_WAIT(2);
        __syncthreads();
        const int st = i % G_STAGES;
        const uint32_t aS = sA0 + st * GA_STAGE;
        const uint32_t bS = sB0 + st * GB_STAGE;

        #pragma unroll
        for (int ks = 0; ks < 32; ks += 16) {
            uint32_t af[2][4];
            #pragma unroll
            for (int mt = 0; mt < 2; mt++)
                ldsm4(af[mt], aS + aFragOff + mt * (16*GA_STRIDE) + ks * 2);
            #pragma unroll
            for (int np = 0; np < 4; np++) {
                uint32_t bf[4];
                ldsm4t(bf, bS + bFragOff + ks * GB_STRIDE + np * 32);
                #pragma unroll
                for (int mt = 0; mt < 2; mt++) {
                    mma16(acc[mt][2*np],   af[mt], bf);
                    mma16(acc[mt][2*np+1], af[mt], bf + 2);
                }
            }
        }
        __syncthreads();
        if (i + G_STAGES < KT) {
            const int kt = i + G_STAGES;
            const __half* Asrc = Abase + kt * 32;
            const __half* Wsrc = Wbase + (size_t)kt * 32 * DMODEL;
            uint32_t a = sA0 + st * GA_STAGE + aDst;
            uint32_t b = sB0 + st * GB_STAGE + bDst;
            cpa16(a,                 Asrc);
            cpa16(a + 64*GA_STRIDE,  Asrc + (size_t)64 * DMODEL);
            cpa16(b,                 Wsrc);
            cpa16(b + 16*GB_STRIDE,  Wsrc + (size_t)16 * DMODEL);
        }
        CP_COMMIT();
    }

    // epilogue
    __half* splitDst = (outMode == 1) ? g_Qh : (outMode == 2) ? g_Kh : g_Vh;
    #pragma unroll
    for (int mt = 0; mt < 2; mt++) {
        #pragma unroll
        for (int nt = 0; nt < 8; nt++) {
            int c = n0 + wn*64 + nt*8 + 2*t;
            float bb0 = bias[c], bb1 = bias[c+1];
            #pragma unroll
            for (int hh = 0; hh < 2; hh++) {
                int r = m0 + wm*32 + mt*16 + g + hh*8;
                float v0 = acc[mt][nt][2*hh]   + bb0;
                float v1 = acc[mt][nt][2*hh+1] + bb1;
                if (outMode == 0) {
                    float2 fv = make_float2(v0, v1);
                    *reinterpret_cast<float2*>(&outF[(size_t)r * DMODEL + c]) = fv;
                } else {
                    int b = r >> 11, l = r & (SEQ-1);
                    int h = c >> 6, d = c & (DHEAD-1);
                    size_t idx = ((((size_t)b*NHEADS + h)*SEQ) + l)*DHEAD + d;
                    *reinterpret_cast<uint32_t*>(&splitDst[idx]) = packh2(v0, v1);
                }
            }
        }
    }
}

// ============================================================================
// Flash attention (R2-validated): causal, fp16 mma. Grid (32, 64), 128 thr.
// BM=BN=64. K/V double-buffered cp.async; P in registers (FA2).
// ============================================================================
#define AT_STRIDE 144            // bytes per smem row (64+8 halves)
#define AT_TILE   (64*AT_STRIDE) // 9216

__global__ __launch_bounds__(128) void attn_kernel()
{
    __shared__ __align__(16) char sm[4 * AT_TILE];
    const uint32_t smBase = smem_u32(sm);
    const uint32_t sK0 = smBase;
    const uint32_t sV0 = smBase + 2*AT_TILE;

    const int tid = threadIdx.x;
    const int warp = tid >> 5, lane = tid & 31;
    const int g = lane >> 2, t = lane & 3;
    const int bh = blockIdx.y;
    const int qt = (int)(gridDim.x - 1 - blockIdx.x);   // longest-first
    const int q0 = qt * 64;

    const __half* Qp = g_Qh + (size_t)bh * SEQ * DHEAD;
    const __half* Kp = g_Kh + (size_t)bh * SEQ * DHEAD;
    const __half* Vp = g_Vh + (size_t)bh * SEQ * DHEAD;

    {
        const __half* Qs = Qp + (size_t)q0 * DHEAD;
        #pragma unroll
        for (int p = 0; p < 4; p++) {
            int idx = tid + p*128;
            int r = idx >> 3, c = idx & 7;
            cpa16(sK0 + AT_TILE + r*AT_STRIDE + c*16, Qs + r*DHEAD + c*8);
        }
        CP_COMMIT();
        #pragma unroll
        for (int p = 0; p < 4; p++) {
            int idx = tid + p*128;
            int r = idx >> 3, c = idx & 7;
            cpa16(sK0 + r*AT_STRIDE + c*16, Kp + r*DHEAD + c*8);
            cpa16(sV0 + r*AT_STRIDE + c*16, Vp + r*DHEAD + c*8);
        }
        CP_COMMIT();
    }
    CP_WAIT(1);
    __syncthreads();

    uint32_t qf[4][4];
    {
        uint32_t qOff = sK0 + AT_TILE + (uint32_t)((warp*16 + (lane & 15)) * AT_STRIDE + (lane >> 4) * 16);
        #pragma unroll
        for (int ks = 0; ks < 4; ks++)
            ldsm4(qf[ks], qOff + ks * 32);
    }
    __syncthreads();

    const uint32_t kOff = (uint32_t)(((lane & 7) + ((lane >> 4) << 3)) * AT_STRIDE + ((lane >> 3) & 1) * 16);
    const uint32_t vOff = (uint32_t)((lane & 15) * AT_STRIDE + (lane >> 4) * 16);

    float oacc[8][4];
    #pragma unroll
    for (int nt = 0; nt < 8; nt++)
        #pragma unroll
        for (int e = 0; e < 4; e++) oacc[nt][e] = 0.f;
    float mrun[2] = {-INFINITY, -INFINITY};
    float lrun[2] = {0.f, 0.f};
    const float cl2e = 0.125f * 1.4426950408889634f;

    for (int j = 0; j <= qt; j++) {
        if (j < qt) {
            const __half* Ks = Kp + (size_t)(j+1) * 64 * DHEAD;
            const __half* Vs = Vp + (size_t)(j+1) * 64 * DHEAD;
            uint32_t kb = sK0 + ((j+1) & 1) * AT_TILE;
            uint32_t vb = sV0 + ((j+1) & 1) * AT_TILE;
            #pragma unroll
            for (int p = 0; p < 4; p++) {
                int idx = tid + p*128;
                int r = idx >> 3, c = idx & 7;
                cpa16(kb + r*AT_STRIDE + c*16, Ks + r*DHEAD + c*8);
                cpa16(vb + r*AT_STRIDE + c*16, Vs + r*DHEAD + c*8);
            }
        }
        CP_COMMIT();
        CP_WAIT(1);
        __syncthreads();

        const uint32_t kB = sK0 + (j & 1) * AT_TILE;
        const uint32_t vB = sV0 + (j & 1) * AT_TILE;

        float s[8][4];
        #pragma unroll
        for (int nt = 0; nt < 8; nt++)
            #pragma unroll
            for (int e = 0; e < 4; e++) s[nt][e] = 0.f;

        #pragma unroll
        for (int ks = 0; ks < 4; ks++) {
            #pragma unroll
            for (int np = 0; np < 4; np++) {
                uint32_t bf[4];
                ldsm4(bf, kB + kOff + np * (16*AT_STRIDE) + ks * 32);
                mma16(s[2*np],   qf[ks], bf);
                mma16(s[2*np+1], qf[ks], bf + 2);
            }
        }

        if (j == qt) {
            #pragma unroll
            for (int nt = 0; nt < 8; nt++) {
                #pragma unroll
                for (int e = 0; e < 4; e++) {
                    int rq = q0 + warp*16 + g + ((e >= 2) ? 8 : 0);
                    int ck = j*64 + nt*8 + 2*t + (e & 1);
                    if (ck > rq) s[nt][e] = -INFINITY;
                }
            }
        }

        #pragma unroll
        for (int hh = 0; hh < 2; hh++) {
            float mx = -INFINITY;
            #pragma unroll
            for (int nt = 0; nt < 8; nt++)
                mx = fmaxf(mx, fmaxf(s[nt][2*hh], s[nt][2*hh+1]));
            mx = fmaxf(mx, __shfl_xor_sync(0xffffffffu, mx, 1));
            mx = fmaxf(mx, __shfl_xor_sync(0xffffffffu, mx, 2));
            float mnew = fmaxf(mrun[hh], mx);
            float corr = ex2f((mrun[hh] - mnew) * cl2e);
            float mc = mnew * cl2e;
            mrun[hh] = mnew;
            float sum = 0.f;
            #pragma unroll
            for (int nt = 0; nt < 8; nt++) {
                float p0 = ex2f(fmaf(s[nt][2*hh],   cl2e, -mc)); s[nt][2*hh]   = p0;
                float p1 = ex2f(fmaf(s[nt][2*hh+1], cl2e, -mc)); s[nt][2*hh+1] = p1;
                sum += p0 + p1;
            }
            sum += __shfl_xor_sync(0xffffffffu, sum, 1);
            sum += __shfl_xor_sync(0xffffffffu, sum, 2);
            lrun[hh] = lrun[hh] * corr + sum;
            #pragma unroll
            for (int nt = 0; nt < 8; nt++) {
                oacc[nt][2*hh]   *= corr;
                oacc[nt][2*hh+1] *= corr;
            }
        }

        #pragma unroll
        for (int kb = 0; kb < 4; kb++) {
            uint32_t pa[4];
            pa[0] = packh2(s[2*kb][0],   s[2*kb][1]);
            pa[1] = packh2(s[2*kb][2],   s[2*kb][3]);
            pa[2] = packh2(s[2*kb+1][0], s[2*kb+1][1]);
            pa[3] = packh2(s[2*kb+1][2], s[2*kb+1][3]);
            #pragma unroll
            for (int np = 0; np < 4; np++) {
                uint32_t bf[4];
                ldsm4t(bf, vB + vOff + kb * (16*AT_STRIDE) + np * 32);
                mma16(oacc[2*np],   pa, bf);
                mma16(oacc[2*np+1], pa, bf + 2);
            }
        }
        __syncthreads();
    }

    const int b = bh / NHEADS, h = bh % NHEADS;
    float linv[2] = {1.f / lrun[0], 1.f / lrun[1]};
    #pragma unroll
    for (int nt = 0; nt < 8; nt++) {
        #pragma unroll
        for (int hh = 0; hh < 2; hh++) {
            int r = q0 + warp*16 + g + hh*8;
            int d = nt*8 + 2*t;
            size_t idx = ((size_t)b*SEQ + r) * DMODEL + h*DHEAD + d;
            *reinterpret_cast<uint32_t*>(&g_Oh[idx]) =
                packh2(oacc[nt][2*hh] * linv[hh], oacc[nt][2*hh+1] * linv[hh]);
        }
    }
}

// ============================================================================
extern "C" void kernel_launch(void* const* d_in, const int* in_sizes, int n_in,
                              void* d_out, int out_size)
{
    const float* q  = (const float*)d_in[0];
    const float* k  = (const float*)d_in[1];
    const float* v  = (const float*)d_in[2];
    const float* Wq = (const float*)d_in[3];
    const float* bq = (const float*)d_in[4];
    const float* Wk = (const float*)d_in[5];
    const float* bk = (const float*)d_in[6];
    const float* Wv = (const float*)d_in[7];
    const float* bv = (const float*)d_in[8];
    const float* Wo = (const float*)d_in[9];
    const float* bo = (const float*)d_in[10];
    float* out = (float*)d_out;

    cudaFuncSetAttribute(gemm_f16, cudaFuncAttributeMaxDynamicSharedMemorySize, G_SMEM);

    // prepass: all conversions in ONE launch
    f2h_all<<<dim3(8192, 7), 256>>>(q, k, v, Wq, Wk, Wv, Wo);

    // Q,K,V projections fused into one launch via blockIdx.z
    gemm_f16<<<dim3(8, 64, 3), 256, G_SMEM>>>(bq, bk, bv, nullptr, 1);

    // attention
    attn_kernel<<<dim3(32, 64), 128>>>();

    // output GEMM
    gemm_f16<<<dim3(8, 64, 1), 256, G_SMEM>>>(bo, nullptr, nullptr, out, 0);
}

// round 8
// speedup vs baseline: 1.2138x; 1.0948x over previous
#include <cuda_runtime.h>
#include <cuda_fp16.h>
#include <cstdint>
#include <math.h>

#define BATCH 4
#define SEQ 2048
#define DMODEL 1024
#define NHEADS 16
#define DHEAD 64
#define MTOT (BATCH*SEQ)   // 8192
#define NIN ((size_t)MTOT*DMODEL)    // 8388608
#define NW  ((size_t)DMODEL*DMODEL)  // 1048576

// ---------------- scratch (device globals: allocation-free) ----------------
__device__ __half g_Ah[(size_t)3*NIN];   // q,k,v converted to half
__device__ __half g_Wh[(size_t)4*NW];    // Wq,Wk,Wv,Wo converted
__device__ __half g_Qh[NIN];             // [B,H,L,Dh]
__device__ __half g_Kh[NIN];
__device__ __half g_Vh[NIN];
__device__ __half g_Oh[NIN];             // attn out [B,L,D] half

// ---------------- asm helpers ----------------
__device__ __forceinline__ void mma16(float* c, const uint32_t* a, const uint32_t* b){
    asm volatile("mma.sync.aligned.m16n8k16.row.col.f32.f16.f16.f32 "
        "{%0,%1,%2,%3}, {%4,%5,%6,%7}, {%8,%9}, {%0,%1,%2,%3};"
        : "+f"(c[0]), "+f"(c[1]), "+f"(c[2]), "+f"(c[3])
        : "r"(a[0]), "r"(a[1]), "r"(a[2]), "r"(a[3]), "r"(b[0]), "r"(b[1]));
}
__device__ __forceinline__ void ldsm4(uint32_t* r, uint32_t addr){
    asm volatile("ldmatrix.sync.aligned.m8n8.x4.shared.b16 {%0,%1,%2,%3}, [%4];"
        : "=r"(r[0]), "=r"(r[1]), "=r"(r[2]), "=r"(r[3]) : "r"(addr));
}
__device__ __forceinline__ void ldsm4t(uint32_t* r, uint32_t addr){
    asm volatile("ldmatrix.sync.aligned.m8n8.x4.trans.shared.b16 {%0,%1,%2,%3}, [%4];"
        : "=r"(r[0]), "=r"(r[1]), "=r"(r[2]), "=r"(r[3]) : "r"(addr));
}
__device__ __forceinline__ void cpa16(uint32_t dst, const void* src){
    asm volatile("cp.async.cg.shared.global [%0], [%1], 16;" :: "r"(dst), "l"(src));
}
#define CP_COMMIT()  asm volatile("cp.async.commit_group;")
#define CP_WAIT(N)   asm volatile("cp.async.wait_group %0;" :: "n"(N))
__device__ __forceinline__ float ex2f(float x){
    float y; asm("ex2.approx.f32 %0, %1;" : "=f"(y) : "f"(x)); return y;
}
__device__ __forceinline__ uint32_t packh2(float a, float b){
    __half2 h = __floats2half2_rn(a, b);
    return *reinterpret_cast<uint32_t*>(&h);
}
__device__ __forceinline__ uint32_t smem_u32(const void* p){
    return (uint32_t)__cvta_generic_to_shared(p);
}

// ---------------- prepass: fp32 -> fp16, all 7 tensors in ONE launch --------
__global__ void f2h_all(const float* __restrict__ q, const float* __restrict__ k,
                        const float* __restrict__ v, const float* __restrict__ Wq,
                        const float* __restrict__ Wk, const float* __restrict__ Wv,
                        const float* __restrict__ Wo)
{
    const int y = blockIdx.y;
    const float* src;
    __half* dst;
    int n4;
    if (y < 3) {
        src = (y == 0) ? q : (y == 1) ? k : v;
        dst = g_Ah + (size_t)y * NIN;
        n4 = (int)(NIN / 4);
    } else {
        if (blockIdx.x >= 1024) return;
        src = (y == 3) ? Wq : (y == 4) ? Wk : (y == 5) ? Wv : Wo;
        dst = g_Wh + (size_t)(y - 3) * NW;
        n4 = (int)(NW / 4);
    }
    int i = blockIdx.x * blockDim.x + threadIdx.x;
    if (i < n4) {
        float4 val = reinterpret_cast<const float4*>(src)[i];
        uint2 o;
        o.x = packh2(val.x, val.y);
        o.y = packh2(val.z, val.w);
        reinterpret_cast<uint2*>(dst)[i] = o;
    }
}

// ============================================================================
// GEMM: C[8192,1024] = A @ W + bias, half in, fp32 acc.
// Block 128x128, 4 warps (2m x 2n), warp tile 64x64, BK=32, 3-stage cp.async.
// 128 threads -> 2 CTAs/SM. mma:ldsm = 32:8 per warp k16-step.
// qkvMode=1: blockIdx.z in {0,1,2} -> Q/K/V projection (head-split fp16 out).
// qkvMode=0: A=g_Oh, W=Wo, fp32 flat out.
// ============================================================================
#define GA_STRIDE 80     // bytes per A smem row (32+8 halves)
#define GB_STRIDE 272    // bytes per B smem row (128+8 halves)
#define GA_STAGE 10240   // 128*80
#define GB_STAGE 8704    // 32*272
#define G_STAGES 3
#define G_SMEM (G_STAGES*(GA_STAGE+GB_STAGE))   // 56832

__global__ __launch_bounds__(128, 2) void gemm_f16(
    const float* __restrict__ b0, const float* __restrict__ b1,
    const float* __restrict__ b2, float* __restrict__ outF, int qkvMode)
{
    const int z = qkvMode ? (int)blockIdx.z : 3;
    const __half* A = qkvMode ? (g_Ah + (size_t)z * NIN) : g_Oh;
    const __half* W = g_Wh + (size_t)z * NW;
    const float* bias = (z == 0 || z == 3) ? b0 : (z == 1) ? b1 : b2;
    const int outMode = qkvMode ? (z + 1) : 0;

    extern __shared__ __align__(16) char sm[];
    const uint32_t smBase = smem_u32(sm);
    const uint32_t sA0 = smBase;
    const uint32_t sB0 = smBase + G_STAGES * GA_STAGE;

    const int tid = threadIdx.x;
    const int warpId = tid >> 5, lane = tid & 31;
    const int g = lane >> 2, t = lane & 3;
    const int wm = warpId & 1;        // 2 warps along M (64 rows each)
    const int wn = warpId >> 1;       // 2 warps along N (64 cols each)
    const int m0 = blockIdx.y * 128;
    const int n0 = blockIdx.x * 128;

    // cp.async coords (128 threads)
    const int ar = tid >> 2, ac = tid & 3;     // A: rows ar+32p (p=0..3), 4 chunks/row
    const int br = tid >> 4, bc = tid & 15;    // B: rows br+8p (p=0..3), 16 chunks/row
    const __half* Abase = A + (size_t)(m0 + ar) * DMODEL + ac * 8;
    const __half* Wbase = W + (size_t)br * DMODEL + n0 + bc * 8;
    const uint32_t aDst = ar * GA_STRIDE + ac * 16;
    const uint32_t bDst = br * GB_STRIDE + bc * 16;

    // ldmatrix per-lane offsets
    const uint32_t aFragOff = (uint32_t)((wm*64 + (lane & 15)) * GA_STRIDE + (lane >> 4) * 16);
    const uint32_t bFragOff = (uint32_t)((lane & 15) * GB_STRIDE + wn*128 + (lane >> 4) * 16);

    float acc[4][8][4];
    #pragma unroll
    for (int mt = 0; mt < 4; mt++)
        #pragma unroll
        for (int nt = 0; nt < 8; nt++)
            #pragma unroll
            for (int e = 0; e < 4; e++) acc[mt][nt][e] = 0.f;

    const int KT = DMODEL / 32;  // 32 k-tiles

    #pragma unroll
    for (int s = 0; s < G_STAGES; s++) {
        const __half* Asrc = Abase + s * 32;
        const __half* Wsrc = Wbase + (size_t)s * 32 * DMODEL;
        uint32_t a = sA0 + s * GA_STAGE + aDst;
        uint32_t b = sB0 + s * GB_STAGE + bDst;
        #pragma unroll
        for (int p = 0; p < 4; p++) {
            cpa16(a + p * (32*GA_STRIDE), Asrc + (size_t)p * 32 * DMODEL);
            cpa16(b + p * (8*GB_STRIDE),  Wsrc + (size_t)p * 8  * DMODEL);
        }
        CP_COMMIT();
    }

    for (int i = 0; i < KT; i++) {
        CP_WAIT(2);
        __syncthreads();
        const int st = i % G_STAGES;
        const uint32_t aS = sA0 + st * GA_STAGE;
        const uint32_t bS = sB0 + st * GB_STAGE;

        #pragma unroll
        for (int ks = 0; ks < 32; ks += 16) {
            uint32_t af[4][4], bf[4][4];
            #pragma unroll
            for (int mt = 0; mt < 4; mt++)
                ldsm4(af[mt], aS + aFragOff + mt * (16*GA_STRIDE) + ks * 2);
            #pragma unroll
            for (int np = 0; np < 4; np++)
                ldsm4t(bf[np], bS + bFragOff + ks * GB_STRIDE + np * 32);
            #pragma unroll
            for (int mt = 0; mt < 4; mt++)
                #pragma unroll
                for (int np = 0; np < 4; np++) {
                    mma16(acc[mt][2*np],   af[mt], bf[np]);
                    mma16(acc[mt][2*np+1], af[mt], bf[np] + 2);
                }
        }
        __syncthreads();
        if (i + G_STAGES < KT) {
            const int kt = i + G_STAGES;
            const __half* Asrc = Abase + kt * 32;
            const __half* Wsrc = Wbase + (size_t)kt * 32 * DMODEL;
            uint32_t a = sA0 + st * GA_STAGE + aDst;
            uint32_t b = sB0 + st * GB_STAGE + bDst;
            #pragma unroll
            for (int p = 0; p < 4; p++) {
                cpa16(a + p * (32*GA_STRIDE), Asrc + (size_t)p * 32 * DMODEL);
                cpa16(b + p * (8*GB_STRIDE),  Wsrc + (size_t)p * 8  * DMODEL);
            }
        }
        CP_COMMIT();
    }

    // epilogue
    __half* splitDst = (outMode == 1) ? g_Qh : (outMode == 2) ? g_Kh : g_Vh;
    #pragma unroll
    for (int mt = 0; mt < 4; mt++) {
        #pragma unroll
        for (int nt = 0; nt < 8; nt++) {
            int c = n0 + wn*64 + nt*8 + 2*t;
            float bb0 = bias[c], bb1 = bias[c+1];
            #pragma unroll
            for (int hh = 0; hh < 2; hh++) {
                int r = m0 + wm*64 + mt*16 + g + hh*8;
                float v0 = acc[mt][nt][2*hh]   + bb0;
                float v1 = acc[mt][nt][2*hh+1] + bb1;
                if (outMode == 0) {
                    float2 fv = make_float2(v0, v1);
                    *reinterpret_cast<float2*>(&outF[(size_t)r * DMODEL + c]) = fv;
                } else {
                    int b = r >> 11, l = r & (SEQ-1);
                    int h = c >> 6, d = c & (DHEAD-1);
                    size_t idx = ((((size_t)b*NHEADS + h)*SEQ) + l)*DHEAD + d;
                    *reinterpret_cast<uint32_t*>(&splitDst[idx]) = packh2(v0, v1);
                }
            }
        }
    }
}

// ============================================================================
// Flash attention (R2-validated): causal, fp16 mma. Grid (32, 64), 128 thr.
// BM=BN=64. K/V double-buffered cp.async; P in registers (FA2).
// ============================================================================
#define AT_STRIDE 144            // bytes per smem row (64+8 halves)
#define AT_TILE   (64*AT_STRIDE) // 9216

__global__ __launch_bounds__(128) void attn_kernel()
{
    __shared__ __align__(16) char sm[4 * AT_TILE];
    const uint32_t smBase = smem_u32(sm);
    const uint32_t sK0 = smBase;
    const uint32_t sV0 = smBase + 2*AT_TILE;

    const int tid = threadIdx.x;
    const int warp = tid >> 5, lane = tid & 31;
    const int g = lane >> 2, t = lane & 3;
    const int bh = blockIdx.y;
    const int qt = (int)(gridDim.x - 1 - blockIdx.x);   // longest-first
    const int q0 = qt * 64;

    const __half* Qp = g_Qh + (size_t)bh * SEQ * DHEAD;
    const __half* Kp = g_Kh + (size_t)bh * SEQ * DHEAD;
    const __half* Vp = g_Vh + (size_t)bh * SEQ * DHEAD;

    {
        const __half* Qs = Qp + (size_t)q0 * DHEAD;
        #pragma unroll
        for (int p = 0; p < 4; p++) {
            int idx = tid + p*128;
            int r = idx >> 3, c = idx & 7;
            cpa16(sK0 + AT_TILE + r*AT_STRIDE + c*16, Qs + r*DHEAD + c*8);
        }
        CP_COMMIT();
        #pragma unroll
        for (int p = 0; p < 4; p++) {
            int idx = tid + p*128;
            int r = idx >> 3, c = idx & 7;
            cpa16(sK0 + r*AT_STRIDE + c*16, Kp + r*DHEAD + c*8);
            cpa16(sV0 + r*AT_STRIDE + c*16, Vp + r*DHEAD + c*8);
        }
        CP_COMMIT();
    }
    CP_WAIT(1);
    __syncthreads();

    uint32_t qf[4][4];
    {
        uint32_t qOff = sK0 + AT_TILE + (uint32_t)((warp*16 + (lane & 15)) * AT_STRIDE + (lane >> 4) * 16);
        #pragma unroll
        for (int ks = 0; ks < 4; ks++)
            ldsm4(qf[ks], qOff + ks * 32);
    }
    __syncthreads();

    const uint32_t kOff = (uint32_t)(((lane & 7) + ((lane >> 4) << 3)) * AT_STRIDE + ((lane >> 3) & 1) * 16);
    const uint32_t vOff = (uint32_t)((lane & 15) * AT_STRIDE + (lane >> 4) * 16);

    float oacc[8][4];
    #pragma unroll
    for (int nt = 0; nt < 8; nt++)
        #pragma unroll
        for (int e = 0; e < 4; e++) oacc[nt][e] = 0.f;
    float mrun[2] = {-INFINITY, -INFINITY};
    float lrun[2] = {0.f, 0.f};
    const float cl2e = 0.125f * 1.4426950408889634f;

    for (int j = 0; j <= qt; j++) {
        if (j < qt) {
            const __half* Ks = Kp + (size_t)(j+1) * 64 * DHEAD;
            const __half* Vs = Vp + (size_t)(j+1) * 64 * DHEAD;
            uint32_t kb = sK0 + ((j+1) & 1) * AT_TILE;
            uint32_t vb = sV0 + ((j+1) & 1) * AT_TILE;
            #pragma unroll
            for (int p = 0; p < 4; p++) {
                int idx = tid + p*128;
                int r = idx >> 3, c = idx & 7;
                cpa16(kb + r*AT_STRIDE + c*16, Ks + r*DHEAD + c*8);
                cpa16(vb + r*AT_STRIDE + c*16, Vs + r*DHEAD + c*8);
            }
        }
        CP_COMMIT();
        CP_WAIT(1);
        __syncthreads();

        const uint32_t kB = sK0 + (j & 1) * AT_TILE;
        const uint32_t vB = sV0 + (j & 1) * AT_TILE;

        float s[8][4];
        #pragma unroll
        for (int nt = 0; nt < 8; nt++)
            #pragma unroll
            for (int e = 0; e < 4; e++) s[nt][e] = 0.f;

        #pragma unroll
        for (int ks = 0; ks < 4; ks++) {
            #pragma unroll
            for (int np = 0; np < 4; np++) {
                uint32_t bf[4];
                ldsm4(bf, kB + kOff + np * (16*AT_STRIDE) + ks * 32);
                mma16(s[2*np],   qf[ks], bf);
                mma16(s[2*np+1], qf[ks], bf + 2);
            }
        }

        if (j == qt) {
            #pragma unroll
            for (int nt = 0; nt < 8; nt++) {
                #pragma unroll
                for (int e = 0; e < 4; e++) {
                    int rq = q0 + warp*16 + g + ((e >= 2) ? 8 : 0);
                    int ck = j*64 + nt*8 + 2*t + (e & 1);
                    if (ck > rq) s[nt][e] = -INFINITY;
                }
            }
        }

        #pragma unroll
        for (int hh = 0; hh < 2; hh++) {
            float mx = -INFINITY;
            #pragma unroll
            for (int nt = 0; nt < 8; nt++)
                mx = fmaxf(mx, fmaxf(s[nt][2*hh], s[nt][2*hh+1]));
            mx = fmaxf(mx, __shfl_xor_sync(0xffffffffu, mx, 1));
            mx = fmaxf(mx, __shfl_xor_sync(0xffffffffu, mx, 2));
            float mnew = fmaxf(mrun[hh], mx);
            float corr = ex2f((mrun[hh] - mnew) * cl2e);
            float mc = mnew * cl2e;
            mrun[hh] = mnew;
            float sum = 0.f;
            #pragma unroll
            for (int nt = 0; nt < 8; nt++) {
                float p0 = ex2f(fmaf(s[nt][2*hh],   cl2e, -mc)); s[nt][2*hh]   = p0;
                float p1 = ex2f(fmaf(s[nt][2*hh+1], cl2e, -mc)); s[nt][2*hh+1] = p1;
                sum += p0 + p1;
            }
            sum += __shfl_xor_sync(0xffffffffu, sum, 1);
            sum += __shfl_xor_sync(0xffffffffu, sum, 2);
            lrun[hh] = lrun[hh] * corr + sum;
            #pragma unroll
            for (int nt = 0; nt < 8; nt++) {
                oacc[nt][2*hh]   *= corr;
                oacc[nt][2*hh+1] *= corr;
            }
        }

        #pragma unroll
        for (int kb = 0; kb < 4; kb++) {
            uint32_t pa[4];
            pa[0] = packh2(s[2*kb][0],   s[2*kb][1]);
            pa[1] = packh2(s[2*kb][2],   s[2*kb][3]);
            pa[2] = packh2(s[2*kb+1][0], s[2*kb+1][1]);
            pa[3] = packh2(s[2*kb+1][2], s[2*kb+1][3]);
            #pragma unroll
            for (int np = 0; np < 4; np++) {
                uint32_t bf[4];
                ldsm4t(bf, vB + vOff + kb * (16*AT_STRIDE) + np * 32);
                mma16(oacc[2*np],   pa, bf);
                mma16(oacc[2*np+1], pa, bf + 2);
            }
        }
        __syncthreads();
    }

    const int b = bh / NHEADS, h = bh % NHEADS;
    float linv[2] = {1.f / lrun[0], 1.f / lrun[1]};
    #pragma unroll
    for (int nt = 0; nt < 8; nt++) {
        #pragma unroll
        for (int hh = 0; hh < 2; hh++) {
            int r = q0 + warp*16 + g + hh*8;
            int d = nt*8 + 2*t;
            size_t idx = ((size_t)b*SEQ + r) * DMODEL + h*DHEAD + d;
            *reinterpret_cast<uint32_t*>(&g_Oh[idx]) =
                packh2(oacc[nt][2*hh] * linv[hh], oacc[nt][2*hh+1] * linv[hh]);
        }
    }
}

// ============================================================================
extern "C" void kernel_launch(void* const* d_in, const int* in_sizes, int n_in,
                              void* d_out, int out_size)
{
    const float* q  = (const float*)d_in[0];
    const float* k  = (const float*)d_in[1];
    const float* v  = (const float*)d_in[2];
    const float* Wq = (const float*)d_in[3];
    const float* bq = (const float*)d_in[4];
    const float* Wk = (const float*)d_in[5];
    const float* bk = (const float*)d_in[6];
    const float* Wv = (const float*)d_in[7];
    const float* bv = (const float*)d_in[8];
    const float* Wo = (const float*)d_in[9];
    const float* bo = (const float*)d_in[10];
    float* out = (float*)d_out;

    cudaFuncSetAttribute(gemm_f16, cudaFuncAttributeMaxDynamicSharedMemorySize, G_SMEM);

    // prepass: all conversions in ONE launch
    f2h_all<<<dim3(8192, 7), 256>>>(q, k, v, Wq, Wk, Wv, Wo);

    // Q,K,V projections fused into one launch via blockIdx.z
    gemm_f16<<<dim3(8, 64, 3), 128, G_SMEM>>>(bq, bk, bv, nullptr, 1);

    // attention
    attn_kernel<<<dim3(32, 64), 128>>>();

    // output GEMM
    gemm_f16<<<dim3(8, 64, 1), 128, G_SMEM>>>(bo, nullptr, nullptr, out, 0);
}